// round 7
// baseline (speedup 1.0000x reference)
#include <cuda_runtime.h>
#include <cstdint>

// ===========================================================================
// MaskedCouplingRQS — Round 7: 256-row CTA, 2 M-tiles/warp (B-frag reuse x2),
// unit-pipelined weight staging, smem logdet, direct global x_trans/y.
// ===========================================================================

#define THREADS 256
#define SA 136                        // A stride (LDS.64 conflict-free)
#define SW 80                         // W stride (LDS.128 conflict-free)
#define SP 104                        // P stride

// ---- smem float offsets ----
#define A_F    0                      // 256*136 = 34816
#define WB0_F  34816                  // 64*80 = 5120
#define WB1_F  39936
#define P_F    45056                  // 96*104 = 9984
#define B1_F   55040
#define B2_F   55168
#define B3_F   55296
#define B4_F   55424                  // 800
#define LD_F   56224                  // 256
#define SMEM_BYTES (56480 * 4)        // 225,920 B

// ---- packed weights (tf32-rounded, mma-interleaved) ----
#define WPK_W1 0                      // [128][32]   (2 n-units of 64)
#define WPK_W2 4096                   // 4 units [64][64]: k0n0,k0n1,k1n0,k1n1
#define WPK_W3 20480
#define WPK_W4 36864                  // 8 chunks x (k0n0[64],k0n1[40],k1n0[64],k1n1[40])
#define W4_CH  13312                  // floats per chunk
#define WPK_TOT 143360
__device__ float g_wpk[WPK_TOT];

// --------------------------- helpers ---------------------------------------
__device__ __forceinline__ void cp16(float* dst, const float* src) {
    uint32_t s = (uint32_t)__cvta_generic_to_shared(dst);
    asm volatile("cp.async.cg.shared.global [%0], [%1], 16;" :: "r"(s), "l"(src));
}
__device__ __forceinline__ void cp_commit() { asm volatile("cp.async.commit_group;"); }
template<int N>
__device__ __forceinline__ void cp_wait() {
    asm volatile("cp.async.wait_group %0;" :: "n"(N) : "memory");
}
__device__ __forceinline__ uint32_t tf32_rna(float f) {
    uint32_t u;
    asm("cvt.rna.tf32.f32 %0, %1;" : "=r"(u) : "f"(f));
    return u;
}
#define F2U __float_as_uint
__device__ __forceinline__ void mma8(float* c, uint32_t a0, uint32_t a1,
                                     uint32_t a2, uint32_t a3,
                                     uint32_t b0, uint32_t b1) {
    asm volatile(
        "mma.sync.aligned.m16n8k8.row.col.f32.tf32.tf32.f32 "
        "{%0,%1,%2,%3}, {%4,%5,%6,%7}, {%8,%9}, {%0,%1,%2,%3};"
        : "+f"(c[0]), "+f"(c[1]), "+f"(c[2]), "+f"(c[3])
        : "r"(a0), "r"(a1), "r"(a2), "r"(a3), "r"(b0), "r"(b1));
}
__device__ __forceinline__ float softplus_f(float v) {
    return fmaxf(v, 0.f) + __logf(1.f + __expf(-fabsf(v)));
}
__device__ __forceinline__ int apos(int c) {        // interleaved A column
    return ((c >> 3) << 3) + ((c & 3) << 1) + ((c & 7) >> 2);
}

// ---------------------------------------------------------------------------
// prep: pack + tf32-round weights. Within each 16-col K-group, packed
// position q (mq=q>>2, j=q&3) holds logical k = 16*kt2 + mq + 4*j.
// ---------------------------------------------------------------------------
__global__ void prep_weights(const float* __restrict__ W1, const float* __restrict__ W2,
                             const float* __restrict__ W3, const float* __restrict__ W4)
{
    int idx = blockIdx.x * blockDim.x + threadIdx.x;
    if (idx >= WPK_TOT) return;
    float v;
    if (idx < WPK_W2) {                               // W1 [128][32]
        int n = idx >> 5, p = idx & 31;
        int kt2 = p >> 4, q = p & 15, mq = q >> 2, j = q & 3;
        v = W1[n * 32 + kt2 * 16 + mq + 4 * j];
    } else if (idx < WPK_W4) {                        // W2 / W3: 4 units [64][64]
        int t = idx - WPK_W2;
        const float* W = (t < 16384) ? W2 : W3;
        int r = t & 16383;
        int u = r >> 12, rr = r & 4095;
        int nloc = rr >> 6, p = rr & 63;
        int kt2 = p >> 4, q = p & 15, mq = q >> 2, j = q & 3;
        int n = (u & 1) * 64 + nloc;
        int k = (u >> 1) * 64 + kt2 * 16 + mq + 4 * j;
        v = W[n * 128 + k];
    } else {                                          // W4: 8 chunks, padded N=104
        int t = idx - WPK_W4;
        int c = t / W4_CH, r = t % W4_CH;
        int kh, nu, rr;
        if      (r < 4096)  { kh = 0; nu = 0; rr = r; }
        else if (r < 6656)  { kh = 0; nu = 1; rr = r - 4096; }
        else if (r < 10752) { kh = 1; nu = 0; rr = r - 6656; }
        else                { kh = 1; nu = 1; rr = r - 10752; }
        int nloc = rr >> 6, p = rr & 63;
        int kt2 = p >> 4, q = p & 15, mq = q >> 2, j = q & 3;
        int n = nu * 64 + nloc;
        int k = kh * 64 + kt2 * 16 + mq + 4 * j;
        v = (n < 100) ? W4[(size_t)(c * 100 + n) * 128 + k] : 0.f;
    }
    g_wpk[idx] = __uint_as_float(tf32_rna(v));
}

// ---------------------------------------------------------------------------
__device__ __forceinline__ void stage64(float* dst, const float* src, int nrows) {
    for (int i = threadIdx.x; i < nrows * 16; i += THREADS) {
        int row = i >> 4, j = i & 15;
        cp16(dst + row * SW + j * 4, src + row * 64 + j * 4);
    }
}
__device__ __forceinline__ void stage32(float* dst, const float* src, int nrows) {
    for (int i = threadIdx.x; i < nrows * 8; i += THREADS) {
        int row = i >> 3, j = i & 7;
        cp16(dst + row * SW + j * 4, src + row * 32 + j * 4);
    }
}

// MMA over one staged unit: A loads inline (2 m-tiles), W via LDS.128.
template<int NT, int KT2>
__device__ __forceinline__ void mma_unit(const float* a0, const float* a1,
                                         const float* Wg, float* C) {
    #pragma unroll
    for (int kt2 = 0; kt2 < KT2; kt2++) {
        float2 e00 = *(const float2*)(a0 + kt2 * 16);
        float2 e08 = *(const float2*)(a0 + 8 * SA + kt2 * 16);
        float2 o00 = *(const float2*)(a0 + kt2 * 16 + 8);
        float2 o08 = *(const float2*)(a0 + 8 * SA + kt2 * 16 + 8);
        float2 e10 = *(const float2*)(a1 + kt2 * 16);
        float2 e18 = *(const float2*)(a1 + 8 * SA + kt2 * 16);
        float2 o10 = *(const float2*)(a1 + kt2 * 16 + 8);
        float2 o18 = *(const float2*)(a1 + 8 * SA + kt2 * 16 + 8);
        #pragma unroll
        for (int nt = 0; nt < NT; nt++) {
            float4 wb = *(const float4*)(Wg + nt * 8 * SW + kt2 * 16);
            mma8(C + nt * 8,     F2U(e00.x), F2U(e08.x), F2U(e00.y), F2U(e08.y),
                 F2U(wb.x), F2U(wb.y));
            mma8(C + nt * 8 + 4, F2U(e10.x), F2U(e18.x), F2U(e10.y), F2U(e18.y),
                 F2U(wb.x), F2U(wb.y));
            mma8(C + nt * 8,     F2U(o00.x), F2U(o08.x), F2U(o00.y), F2U(o08.y),
                 F2U(wb.z), F2U(wb.w));
            mma8(C + nt * 8 + 4, F2U(o10.x), F2U(o18.x), F2U(o10.y), F2U(o18.y),
                 F2U(wb.z), F2U(wb.w));
        }
    }
}

// relu(C + bias) -> interleaved A tile (own 32 rows), tf32-rounded
__device__ __forceinline__ void relu_store2(const float* C, const float* bs,
                                            float* A, int R0) {
    const int lane = threadIdx.x & 31;
    const int g = lane >> 2, m = lane & 3;
    const int c0b = 2 * m, c1b = 2 * m + 1;
    const int P0 = ((c0b & 3) << 1) + (c0b >> 2);
    const int P1 = ((c1b & 3) << 1) + (c1b >> 2);
    #pragma unroll
    for (int mt = 0; mt < 2; mt++) {
        const int rb = R0 + mt * 16;
        #pragma unroll
        for (int nt = 0; nt < 16; nt++) {
            const float b0 = bs[nt * 8 + c0b], b1 = bs[nt * 8 + c1b];
            const float* Cc = C + nt * 8 + mt * 4;
            A[(rb + g) * SA + nt * 8 + P0]     = __uint_as_float(tf32_rna(fmaxf(Cc[0] + b0, 0.f)));
            A[(rb + g) * SA + nt * 8 + P1]     = __uint_as_float(tf32_rna(fmaxf(Cc[1] + b1, 0.f)));
            A[(rb + g + 8) * SA + nt * 8 + P0] = __uint_as_float(tf32_rna(fmaxf(Cc[2] + b0, 0.f)));
            A[(rb + g + 8) * SA + nt * 8 + P1] = __uint_as_float(tf32_rna(fmaxf(Cc[3] + b1, 0.f)));
        }
    }
}

__device__ __forceinline__ void p_store2(const float* C, float* P, int rloc) {
    const int lane = threadIdx.x & 31;
    const int g = lane >> 2, m = lane & 3;
    #pragma unroll
    for (int mt = 0; mt < 2; mt++) {
        const int rb = rloc + mt * 16;
        #pragma unroll
        for (int nt = 0; nt < 13; nt++) {
            const float* Cc = C + nt * 8 + mt * 4;
            P[(rb + g) * SP + nt * 8 + 2 * m]         = Cc[0];
            P[(rb + g) * SP + nt * 8 + 2 * m + 1]     = Cc[1];
            P[(rb + g + 8) * SP + nt * 8 + 2 * m]     = Cc[2];
            P[(rb + g + 8) * SP + nt * 8 + 2 * m + 1] = Cc[3];
        }
    }
}

#define UPRE()      do { cp_wait<1>(); __syncthreads(); } while (0)
#define UPOST(stmt) do { __syncthreads(); stmt; cp_commit(); } while (0)

// ---------------------------------------------------------------------------
__global__ __launch_bounds__(THREADS, 1)
void rqs_mma_kernel(const float* __restrict__ x,
                    const float* __restrict__ b1, const float* __restrict__ b2,
                    const float* __restrict__ b3, const float* __restrict__ b4,
                    float* __restrict__ out, int B)
{
    extern __shared__ float sm[];
    float* A   = sm + A_F;
    float* WA  = sm + WB0_F;
    float* WB  = sm + WB1_F;
    float* Psm = sm + P_F;
    float* B1S = sm + B1_F;
    float* B2S = sm + B2_F;
    float* B3S = sm + B3_F;
    float* B4S = sm + B4_F;
    float* LDS = sm + LD_F;

    const int tid  = threadIdx.x;
    const int lane = tid & 31;
    const int g    = lane >> 2, m = lane & 3;
    const int R0   = (tid >> 5) * 32;
    const long row0 = (long)blockIdx.x * 256;

    const float* aw0 = A + (R0 + g) * SA + m * 2;
    const float* aw1 = aw0 + 16 * SA;
    const int woff = g * SW + m * 4;

    // ---- G0: W1 n0 + biases ----
    stage32(WA, g_wpk + WPK_W1, 64);
    for (int i = tid; i < 32; i += THREADS) {
        cp16(B1S + i * 4, b1 + i * 4);
        cp16(B2S + i * 4, b2 + i * 4);
        cp16(B3S + i * 4, b3 + i * 4);
    }
    for (int i = tid; i < 200; i += THREADS) cp16(B4S + i * 4, b4 + i * 4);
    cp_commit();
    stage32(WB, g_wpk + WPK_W1 + 2048, 64); cp_commit();   // W1 n1

    // ---- x_masked -> interleaved A (tf32), ld accum zero ----
    for (int i = tid; i < 2048; i += THREADS) {
        int row = i >> 3, j = i & 7;
        float4 v = make_float4(0.f, 0.f, 0.f, 0.f);
        if (row0 + row < B) v = *(const float4*)(x + (row0 + row) * 64 + j * 4);
        float* Ar = A + row * SA;
        Ar[apos(j * 4 + 0)] = __uint_as_float(tf32_rna(v.x));
        Ar[apos(j * 4 + 1)] = __uint_as_float(tf32_rna(v.y));
        Ar[apos(j * 4 + 2)] = __uint_as_float(tf32_rna(v.z));
        Ar[apos(j * 4 + 3)] = __uint_as_float(tf32_rna(v.w));
    }
    if (tid < 256) LDS[tid] = 0.f;

    float C[128];

    // ================= Layer 1 (K=32) =================
    UPRE();                                            // W1 n0 ready
    #pragma unroll
    for (int i = 0; i < 128; i++) C[i] = 0.f;
    mma_unit<8, 2>(aw0, aw1, WA + woff, C);
    UPOST(stage64(WA, g_wpk + WPK_W2, 64));            // W2 k0n0
    UPRE();                                            // W1 n1
    mma_unit<8, 2>(aw0, aw1, WB + woff, C + 64);
    relu_store2(C, B1S, A, R0);                        // h1
    UPOST(stage64(WB, g_wpk + WPK_W2 + 4096, 64));     // W2 k0n1

    // ================= Layer 2 =================
    UPRE();
    #pragma unroll
    for (int i = 0; i < 128; i++) C[i] = 0.f;
    mma_unit<8, 4>(aw0, aw1, WA + woff, C);
    UPOST(stage64(WA, g_wpk + WPK_W2 + 8192, 64));     // W2 k1n0
    UPRE();
    mma_unit<8, 4>(aw0, aw1, WB + woff, C + 64);
    UPOST(stage64(WB, g_wpk + WPK_W2 + 12288, 64));    // W2 k1n1
    UPRE();
    mma_unit<8, 4>(aw0 + 64, aw1 + 64, WA + woff, C);
    UPOST(stage64(WA, g_wpk + WPK_W3, 64));            // W3 k0n0
    UPRE();
    mma_unit<8, 4>(aw0 + 64, aw1 + 64, WB + woff, C + 64);
    relu_store2(C, B2S, A, R0);                        // h2
    UPOST(stage64(WB, g_wpk + WPK_W3 + 4096, 64));     // W3 k0n1

    // ================= Layer 3 =================
    UPRE();
    #pragma unroll
    for (int i = 0; i < 128; i++) C[i] = 0.f;
    mma_unit<8, 4>(aw0, aw1, WA + woff, C);
    UPOST(stage64(WA, g_wpk + WPK_W3 + 8192, 64));     // W3 k1n0
    UPRE();
    mma_unit<8, 4>(aw0, aw1, WB + woff, C + 64);
    UPOST(stage64(WB, g_wpk + WPK_W3 + 12288, 64));    // W3 k1n1
    UPRE();
    mma_unit<8, 4>(aw0 + 64, aw1 + 64, WA + woff, C);
    UPOST(stage64(WA, g_wpk + WPK_W4, 64));            // W4 c0 k0n0
    UPRE();
    mma_unit<8, 4>(aw0 + 64, aw1 + 64, WB + woff, C + 64);
    relu_store2(C, B3S, A, R0);                        // h3
    UPOST(stage64(WB, g_wpk + WPK_W4 + 4096, 40));     // W4 c0 k0n1

    // ================= Layer 4 + spline, 8 chunks =================
    const float MINB = 1e-4f;
    const float FREE = 10.f - 8.f * 1e-4f;

    #pragma unroll 1
    for (int c = 0; c < 8; c++) {
        const float* cw = g_wpk + WPK_W4 + c * W4_CH;
        const float* nw = g_wpk + WPK_W4 + (c + 1) * W4_CH;

        #pragma unroll
        for (int i = 0; i < 104; i++) C[i] = 0.f;

        UPRE();                                        // k0 n0
        mma_unit<8, 4>(aw0, aw1, WA + woff, C);
        UPOST(stage64(WA, cw + 6656, 64));             // k1 n0
        UPRE();                                        // k0 n1
        mma_unit<5, 4>(aw0, aw1, WB + woff, C + 64);
        UPOST(stage64(WB, cw + 10752, 40));            // k1 n1
        UPRE();                                        // k1 n0
        mma_unit<8, 4>(aw0 + 64, aw1 + 64, WA + woff, C);
        if (c < 7) { UPOST(stage64(WA, nw, 64)); }     // next k0n0
        else       { __syncthreads(); }
        if (c < 7) { UPRE(); } else { cp_wait<0>(); __syncthreads(); }
        mma_unit<5, 4>(aw0 + 64, aw1 + 64, WB + woff, C + 64);
        if (c < 7) {
            __syncthreads();
            stage64(WB, nw + 4096, 40);                // next k0n1
            cp_commit();
        }

        // -------- epilogue: 3 row-passes through P --------
        #pragma unroll 1
        for (int pass = 0; pass < 3; pass++) {
            const int rlo = pass * 96;
            const int nr  = (pass < 2) ? 96 : 64;
            __syncthreads();
            if (R0 >= rlo && R0 < rlo + nr) p_store2(C, Psm, R0 - rlo);
            __syncthreads();
            const int ntask = nr * 4;
            #pragma unroll 1
            for (int s = 0; s < 2; s++) {
                const int id = tid + s * 256;
                if (id < ntask) {
                    const int rloc = id >> 2, q = id & 3;
                    const int row  = rlo + rloc;

                    float acc[25];
                    #pragma unroll
                    for (int p = 0; p < 25; p++)
                        acc[p] = Psm[rloc * SP + q * 25 + p] + B4S[c * 100 + q * 25 + p];

                    float mx = acc[0];
                    #pragma unroll
                    for (int i = 1; i < 8; i++) mx = fmaxf(mx, acc[i]);
                    float wdt[8]; float Sw = 0.f;
                    #pragma unroll
                    for (int i = 0; i < 8; i++) { wdt[i] = __expf(acc[i] - mx); Sw += wdt[i]; }
                    float mh = acc[8];
                    #pragma unroll
                    for (int i = 9; i < 16; i++) mh = fmaxf(mh, acc[i]);
                    float hgt[8]; float Sh = 0.f;
                    #pragma unroll
                    for (int i = 0; i < 8; i++) { hgt[i] = __expf(acc[8 + i] - mh); Sh += hgt[i]; }
                    const float fw = FREE / Sw, fh = FREE / Sh;
                    #pragma unroll
                    for (int i = 0; i < 8; i++) {
                        wdt[i] = MINB + wdt[i] * fw;
                        hgt[i] = MINB + hgt[i] * fh;
                    }

                    float xt = 0.f;
                    const bool vr = (row0 + row) < B;
                    if (vr) xt = x[(row0 + row) * 64 + 32 + c * 4 + q];
                    const float xc = fminf(fmaxf(xt, -5.f), 5.f);
                    const bool inside = (xt >= -5.f) && (xt <= 5.f);

                    int idx = 0; float cum = -5.f, xk = -5.f, wk = wdt[0];
                    #pragma unroll
                    for (int i = 0; i < 7; i++) {
                        cum += wdt[i];
                        if (xc >= cum) { idx = i + 1; xk = cum; wk = wdt[i + 1]; }
                    }
                    float cumh = -5.f, yk = -5.f, hk = hgt[0];
                    #pragma unroll
                    for (int i = 0; i < 7; i++) {
                        cumh += hgt[i];
                        if (idx > i) { yk = cumh; hk = hgt[i + 1]; }
                    }
                    float sA = acc[16], sB = acc[17];
                    #pragma unroll
                    for (int i = 1; i < 8; i++)
                        if (idx >= i) { sA = acc[16 + i]; sB = acc[17 + i]; }
                    const float dk  = 1e-4f + softplus_f(sA);
                    const float dk1 = 1e-4f + softplus_f(sB);

                    const float rwk  = 1.f / wk;
                    const float xi   = (xc - xk) * rwk;
                    const float om   = 1.f - xi;
                    const float sk   = hk * rwk;
                    const float xiom = xi * om;
                    const float den  = sk + (dk1 + dk - 2.f * sk) * xiom;
                    const float rden = 1.f / den;
                    const float num  = sk * xi * xi + dk * xiom;
                    const float y_in = yk + hk * num * rden;
                    const float num2 = dk1 * xi * xi + 2.f * sk * xiom + dk * om * om;
                    const float ld_in = __logf(sk * sk * num2 * rden * rden);

                    if (vr) out[(row0 + row) * 64 + 32 + c * 4 + q] = inside ? y_in : xt;

                    float ldv = inside ? ld_in : 0.f;
                    ldv += __shfl_xor_sync(0xffffffffu, ldv, 1);
                    ldv += __shfl_xor_sync(0xffffffffu, ldv, 2);
                    if (q == 0) LDS[row] += ldv;
                }
            }
        }
    }

    // ---- logdet + masked-column copy ----
    __syncthreads();
    if (row0 + tid < B) out[(size_t)B * 64 + row0 + tid] = LDS[tid];
    for (int i = tid; i < 2048; i += THREADS) {
        int row = i >> 3, j = i & 7;
        if (row0 + row < B)
            *(float4*)(out + (row0 + row) * 64 + j * 4) =
                *(const float4*)(x + (row0 + row) * 64 + j * 4);
    }
}

// ---------------------------------------------------------------------------
extern "C" void kernel_launch(void* const* d_in, const int* in_sizes, int n_in,
                              void* d_out, int out_size)
{
    const float* x  = (const float*)d_in[0];
    const float* W1 = (const float*)d_in[1];
    const float* b1 = (const float*)d_in[2];
    const float* W2 = (const float*)d_in[3];
    const float* b2 = (const float*)d_in[4];
    const float* W3 = (const float*)d_in[5];
    const float* b3 = (const float*)d_in[6];
    const float* W4 = (const float*)d_in[7];
    const float* b4 = (const float*)d_in[8];
    float* out = (float*)d_out;

    const int B = in_sizes[0] / 64;

    prep_weights<<<(WPK_TOT + 255) / 256, 256>>>(W1, W2, W3, W4);

    cudaFuncSetAttribute(rqs_mma_kernel,
                         cudaFuncAttributeMaxDynamicSharedMemorySize, SMEM_BYTES);
    const int grid = (B + 255) / 256;
    rqs_mma_kernel<<<grid, THREADS, SMEM_BYTES>>>(x, b1, b2, b3, b4, out, B);
}

// round 8
// speedup vs baseline: 1.0154x; 1.0154x over previous
#include <cuda_runtime.h>
#include <cstdint>

// ===========================================================================
// MaskedCouplingRQS — Round 8: R6 warp shape (16 rows/warp) + 2 CTAs/SM.
// Smem cut to ~107KB: 64-row W units (SW=68), P overlays W buffers in the
// epilogue (2 passes of 64 rows). x_trans/y direct to global.
// ===========================================================================

#define THREADS 256
#define SA 136                        // A stride (LDS.64 conflict-free)
#define SW 68                         // W stride (LDS.128 conflict-free: 68≡4 mod 32)
#define SPP 104                       // P stride

// ---- smem float offsets ----
#define A_F    0                      // 128*136 = 17408
#define WB0_F  17408                  // 64*68 = 4352
#define WB1_F  21760                  // 4352
#define P_F    WB0_F                  // overlay: 64*104 = 6656 <= 8704
#define B1_F   26112
#define B2_F   26240
#define B3_F   26368
#define B4_F   26496                  // 800
#define LD_F   27296                  // 128
#define SMEM_BYTES (27424 * 4)        // 109,696 B  (2 CTAs/SM: 219.4KB)

// ---- packed weights (tf32-rounded, mma-interleaved) — R7 layout, verified ----
#define WPK_W1 0                      // [128][32] rows
#define WPK_W2 4096                   // 4 units [64][64]: k0n0,k0n1,k1n0,k1n1
#define WPK_W3 20480
#define WPK_W4 36864                  // 8 chunks x (k0n0[64],k0n1[40],k1n0[64],k1n1[40])
#define W4_CH  13312
#define WPK_TOT 143360
__device__ float g_wpk[WPK_TOT];

// --------------------------- helpers ---------------------------------------
__device__ __forceinline__ void cp16(float* dst, const float* src) {
    uint32_t s = (uint32_t)__cvta_generic_to_shared(dst);
    asm volatile("cp.async.cg.shared.global [%0], [%1], 16;" :: "r"(s), "l"(src));
}
__device__ __forceinline__ void cp_commit() { asm volatile("cp.async.commit_group;"); }
template<int N>
__device__ __forceinline__ void cp_wait() {
    asm volatile("cp.async.wait_group %0;" :: "n"(N) : "memory");
}
__device__ __forceinline__ uint32_t tf32_rna(float f) {
    uint32_t u;
    asm("cvt.rna.tf32.f32 %0, %1;" : "=r"(u) : "f"(f));
    return u;
}
#define F2U __float_as_uint
__device__ __forceinline__ void mma8(float* c, uint32_t a0, uint32_t a1,
                                     uint32_t a2, uint32_t a3,
                                     uint32_t b0, uint32_t b1) {
    asm volatile(
        "mma.sync.aligned.m16n8k8.row.col.f32.tf32.tf32.f32 "
        "{%0,%1,%2,%3}, {%4,%5,%6,%7}, {%8,%9}, {%0,%1,%2,%3};"
        : "+f"(c[0]), "+f"(c[1]), "+f"(c[2]), "+f"(c[3])
        : "r"(a0), "r"(a1), "r"(a2), "r"(a3), "r"(b0), "r"(b1));
}
__device__ __forceinline__ float softplus_f(float v) {
    return fmaxf(v, 0.f) + __logf(1.f + __expf(-fabsf(v)));
}
__device__ __forceinline__ int apos(int c) {
    return ((c >> 3) << 3) + ((c & 3) << 1) + ((c & 7) >> 2);
}

// ---------------------------------------------------------------------------
// prep (R7, numerics-verified): packed position q (mq=q>>2, j=q&3) holds
// logical k = 16*kt2 + mq + 4*j within each 16-col K-group.
// ---------------------------------------------------------------------------
__global__ void prep_weights(const float* __restrict__ W1, const float* __restrict__ W2,
                             const float* __restrict__ W3, const float* __restrict__ W4)
{
    int idx = blockIdx.x * blockDim.x + threadIdx.x;
    if (idx >= WPK_TOT) return;
    float v;
    if (idx < WPK_W2) {                               // W1 [128][32]
        int n = idx >> 5, p = idx & 31;
        int kt2 = p >> 4, q = p & 15, mq = q >> 2, j = q & 3;
        v = W1[n * 32 + kt2 * 16 + mq + 4 * j];
    } else if (idx < WPK_W4) {                        // W2 / W3: 4 units [64][64]
        int t = idx - WPK_W2;
        const float* W = (t < 16384) ? W2 : W3;
        int r = t & 16383;
        int u = r >> 12, rr = r & 4095;
        int nloc = rr >> 6, p = rr & 63;
        int kt2 = p >> 4, q = p & 15, mq = q >> 2, j = q & 3;
        int n = (u & 1) * 64 + nloc;
        int k = (u >> 1) * 64 + kt2 * 16 + mq + 4 * j;
        v = W[n * 128 + k];
    } else {                                          // W4: 8 chunks, N padded 104
        int t = idx - WPK_W4;
        int c = t / W4_CH, r = t % W4_CH;
        int kh, nu, rr;
        if      (r < 4096)  { kh = 0; nu = 0; rr = r; }
        else if (r < 6656)  { kh = 0; nu = 1; rr = r - 4096; }
        else if (r < 10752) { kh = 1; nu = 0; rr = r - 6656; }
        else                { kh = 1; nu = 1; rr = r - 10752; }
        int nloc = rr >> 6, p = rr & 63;
        int kt2 = p >> 4, q = p & 15, mq = q >> 2, j = q & 3;
        int n = nu * 64 + nloc;
        int k = kh * 64 + kt2 * 16 + mq + 4 * j;
        v = (n < 100) ? W4[(size_t)(c * 100 + n) * 128 + k] : 0.f;
    }
    g_wpk[idx] = __uint_as_float(tf32_rna(v));
}

// ---------------------------------------------------------------------------
template<int ROWFL>
__device__ __forceinline__ void stage_u(float* dst, const float* src, int nrows) {
    constexpr int CH = ROWFL / 4;
    for (int i = threadIdx.x; i < nrows * CH; i += THREADS) {
        int row = i / CH, j = i - row * CH;
        cp16(dst + row * SW + j * 4, src + row * ROWFL + j * 4);
    }
}

// MMA over one staged 64-row unit (R6 fragment scheme, 1 m-tile/warp).
template<int NT, int KT2>
__device__ __forceinline__ void mma_tiles(const float* As, const float* Wg, float* C) {
    #pragma unroll
    for (int kt2 = 0; kt2 < KT2; kt2++) {
        float2 ae0 = *(const float2*)(As + kt2 * 16);
        float2 ae8 = *(const float2*)(As + 8 * SA + kt2 * 16);
        float2 ao0 = *(const float2*)(As + kt2 * 16 + 8);
        float2 ao8 = *(const float2*)(As + 8 * SA + kt2 * 16 + 8);
        #pragma unroll
        for (int nt = 0; nt < NT; nt++) {
            float4 wb = *(const float4*)(Wg + nt * 8 * SW + kt2 * 16);
            mma8(C + nt * 4, F2U(ae0.x), F2U(ae8.x), F2U(ae0.y), F2U(ae8.y),
                 F2U(wb.x), F2U(wb.y));
            mma8(C + nt * 4, F2U(ao0.x), F2U(ao8.x), F2U(ao0.y), F2U(ao8.y),
                 F2U(wb.z), F2U(wb.w));
        }
    }
}

// relu(C + bias) -> interleaved A tile (own 16 rows), tf32-rounded (R6)
__device__ __forceinline__ void relu_store(const float* C, const float* bs,
                                           float* A, int R0) {
    const int lane = threadIdx.x & 31;
    const int g = lane >> 2, m = lane & 3;
    const int c0b = 2 * m, c1b = 2 * m + 1;
    const int P0 = ((c0b & 3) << 1) + (c0b >> 2);
    const int P1 = ((c1b & 3) << 1) + (c1b >> 2);
    #pragma unroll
    for (int nt = 0; nt < 16; nt++) {
        const int c0 = nt * 8 + c0b, c1 = nt * 8 + c1b;
        const float b0 = bs[c0], b1 = bs[c1];
        A[(R0 + g) * SA + nt * 8 + P0]     = __uint_as_float(tf32_rna(fmaxf(C[nt*4+0] + b0, 0.f)));
        A[(R0 + g) * SA + nt * 8 + P1]     = __uint_as_float(tf32_rna(fmaxf(C[nt*4+1] + b1, 0.f)));
        A[(R0 + g + 8) * SA + nt * 8 + P0] = __uint_as_float(tf32_rna(fmaxf(C[nt*4+2] + b0, 0.f)));
        A[(R0 + g + 8) * SA + nt * 8 + P1] = __uint_as_float(tf32_rna(fmaxf(C[nt*4+3] + b1, 0.f)));
    }
}

__device__ __forceinline__ void p_store(const float* C, float* P, int rloc) {
    const int lane = threadIdx.x & 31;
    const int g = lane >> 2, m = lane & 3;
    #pragma unroll
    for (int nt = 0; nt < 13; nt++) {
        const int c0 = nt * 8 + 2 * m, c1 = c0 + 1;
        P[(rloc + g) * SPP + c0]     = C[nt*4+0];
        P[(rloc + g) * SPP + c1]     = C[nt*4+1];
        P[(rloc + g + 8) * SPP + c0] = C[nt*4+2];
        P[(rloc + g + 8) * SPP + c1] = C[nt*4+3];
    }
}

// ---------------------------------------------------------------------------
__global__ __launch_bounds__(THREADS, 2)
void rqs_mma_kernel(const float* __restrict__ x,
                    const float* __restrict__ b1, const float* __restrict__ b2,
                    const float* __restrict__ b3, const float* __restrict__ b4,
                    float* __restrict__ out, int B)
{
    extern __shared__ float sm[];
    float* A   = sm + A_F;
    float* WA  = sm + WB0_F;
    float* WB  = sm + WB1_F;
    float* Psm = sm + P_F;
    float* B1S = sm + B1_F;
    float* B2S = sm + B2_F;
    float* B3S = sm + B3_F;
    float* B4S = sm + B4_F;
    float* LDS = sm + LD_F;

    const int tid  = threadIdx.x;
    const int lane = tid & 31;
    const int g    = lane >> 2, m = lane & 3;
    const int R0   = (tid >> 5) * 16;
    const long row0 = (long)blockIdx.x * 128;

    const float* aw = A + (R0 + g) * SA + m * 2;     // own-warp A base
    const int woff = g * SW + m * 4;

    // ---- prologue staging: W1 n0 (+biases) | W1 n1 ----
    stage_u<32>(WA, g_wpk + WPK_W1, 64);
    for (int i = tid; i < 32; i += THREADS) {
        cp16(B1S + i * 4, b1 + i * 4);
        cp16(B2S + i * 4, b2 + i * 4);
        cp16(B3S + i * 4, b3 + i * 4);
    }
    for (int i = tid; i < 200; i += THREADS) cp16(B4S + i * 4, b4 + i * 4);
    cp_commit();
    stage_u<32>(WB, g_wpk + WPK_W1 + 2048, 64); cp_commit();

    // ---- x_masked -> interleaved A (tf32) ----
    for (int i = tid; i < 1024; i += THREADS) {
        int row = i >> 3, j = i & 7;
        float4 v = make_float4(0.f, 0.f, 0.f, 0.f);
        if (row0 + row < B) v = *(const float4*)(x + (row0 + row) * 64 + j * 4);
        float* Ar = A + row * SA;
        Ar[apos(j * 4 + 0)] = __uint_as_float(tf32_rna(v.x));
        Ar[apos(j * 4 + 1)] = __uint_as_float(tf32_rna(v.y));
        Ar[apos(j * 4 + 2)] = __uint_as_float(tf32_rna(v.z));
        Ar[apos(j * 4 + 3)] = __uint_as_float(tf32_rna(v.w));
    }
    if (tid < 128) LDS[tid] = 0.f;

    cp_wait<0>(); __syncthreads();

    float C[64];

    // ================= Layer 1 (K=32) =================
    #pragma unroll
    for (int i = 0; i < 64; i++) C[i] = 0.f;
    mma_tiles<8, 2>(aw, WA + woff, C);
    __syncthreads(); stage_u<64>(WA, g_wpk + WPK_W2, 64); cp_commit();        // W2 k0n0
    mma_tiles<8, 2>(aw, WB + woff, C + 32);
    relu_store(C, B1S, A, R0);                                                // h1
    __syncthreads(); stage_u<64>(WB, g_wpk + WPK_W2 + 4096, 64); cp_commit(); // W2 k0n1

    // ================= Layer 2 =================
    #pragma unroll
    for (int i = 0; i < 64; i++) C[i] = 0.f;
    cp_wait<1>(); __syncthreads();
    mma_tiles<8, 4>(aw, WA + woff, C);
    __syncthreads(); stage_u<64>(WA, g_wpk + WPK_W2 + 8192, 64); cp_commit(); // k1n0
    cp_wait<1>(); __syncthreads();
    mma_tiles<8, 4>(aw, WB + woff, C + 32);
    __syncthreads(); stage_u<64>(WB, g_wpk + WPK_W2 + 12288, 64); cp_commit();// k1n1
    cp_wait<1>(); __syncthreads();
    mma_tiles<8, 4>(aw + 64, WA + woff, C);
    __syncthreads(); stage_u<64>(WA, g_wpk + WPK_W3, 64); cp_commit();        // W3 k0n0
    cp_wait<1>(); __syncthreads();
    mma_tiles<8, 4>(aw + 64, WB + woff, C + 32);
    relu_store(C, B2S, A, R0);                                                // h2
    __syncthreads(); stage_u<64>(WB, g_wpk + WPK_W3 + 4096, 64); cp_commit(); // W3 k0n1

    // ================= Layer 3 =================
    #pragma unroll
    for (int i = 0; i < 64; i++) C[i] = 0.f;
    cp_wait<1>(); __syncthreads();
    mma_tiles<8, 4>(aw, WA + woff, C);
    __syncthreads(); stage_u<64>(WA, g_wpk + WPK_W3 + 8192, 64); cp_commit(); // k1n0
    cp_wait<1>(); __syncthreads();
    mma_tiles<8, 4>(aw, WB + woff, C + 32);
    __syncthreads(); stage_u<64>(WB, g_wpk + WPK_W3 + 12288, 64); cp_commit();// k1n1
    cp_wait<1>(); __syncthreads();
    mma_tiles<8, 4>(aw + 64, WA + woff, C);
    __syncthreads(); stage_u<64>(WA, g_wpk + WPK_W4, 64); cp_commit();        // W4 c0 k0n0
    cp_wait<1>(); __syncthreads();
    mma_tiles<8, 4>(aw + 64, WB + woff, C + 32);
    relu_store(C, B3S, A, R0);                                                // h3
    __syncthreads(); stage_u<64>(WB, g_wpk + WPK_W4 + 4096, 40); cp_commit(); // c0 k0n1

    // ================= Layer 4 + spline, 8 chunks =================
    const float MINB = 1e-4f;
    const float FREE = 10.f - 8.f * 1e-4f;

    #pragma unroll 1
    for (int c = 0; c < 8; c++) {
        const float* cw = g_wpk + WPK_W4 + c * W4_CH;
        const float* nw = g_wpk + WPK_W4 + (c + 1) * W4_CH;

        #pragma unroll
        for (int i = 0; i < 52; i++) C[i] = 0.f;

        cp_wait<0>(); __syncthreads();                       // k0n0 + k0n1 landed
        mma_tiles<8, 4>(aw, WA + woff, C);
        __syncthreads(); stage_u<64>(WA, cw + 6656, 64); cp_commit();   // k1n0
        mma_tiles<5, 4>(aw, WB + woff, C + 32);
        __syncthreads(); stage_u<64>(WB, cw + 10752, 40); cp_commit();  // k1n1
        cp_wait<1>(); __syncthreads();
        mma_tiles<8, 4>(aw + 64, WA + woff, C);
        cp_wait<0>(); __syncthreads();
        mma_tiles<5, 4>(aw + 64, WB + woff, C + 32);
        __syncthreads();                                     // all mma done; W bufs free

        // -------- epilogue: 2 passes of 64 rows through P (overlaying W bufs)
        #pragma unroll 1
        for (int pass = 0; pass < 2; pass++) {
            if ((R0 >> 6) == pass) p_store(C, Psm, R0 & 63);
            __syncthreads();
            {
                const int rloc = tid >> 2, q = tid & 3;
                const int row  = pass * 64 + rloc;

                float acc[25];
                #pragma unroll
                for (int p = 0; p < 25; p++)
                    acc[p] = Psm[rloc * SPP + q * 25 + p] + B4S[c * 100 + q * 25 + p];

                float mx = acc[0];
                #pragma unroll
                for (int i = 1; i < 8; i++) mx = fmaxf(mx, acc[i]);
                float wdt[8]; float Sw = 0.f;
                #pragma unroll
                for (int i = 0; i < 8; i++) { wdt[i] = __expf(acc[i] - mx); Sw += wdt[i]; }
                float mh = acc[8];
                #pragma unroll
                for (int i = 9; i < 16; i++) mh = fmaxf(mh, acc[i]);
                float hgt[8]; float Sh = 0.f;
                #pragma unroll
                for (int i = 0; i < 8; i++) { hgt[i] = __expf(acc[8 + i] - mh); Sh += hgt[i]; }
                const float fw = FREE / Sw, fh = FREE / Sh;
                #pragma unroll
                for (int i = 0; i < 8; i++) {
                    wdt[i] = MINB + wdt[i] * fw;
                    hgt[i] = MINB + hgt[i] * fh;
                }

                float xt = 0.f;
                const bool vr = (row0 + row) < B;
                if (vr) xt = x[(row0 + row) * 64 + 32 + c * 4 + q];
                const float xc = fminf(fmaxf(xt, -5.f), 5.f);
                const bool inside = (xt >= -5.f) && (xt <= 5.f);

                int idx = 0; float cum = -5.f, xk = -5.f, wk = wdt[0];
                #pragma unroll
                for (int i = 0; i < 7; i++) {
                    cum += wdt[i];
                    if (xc >= cum) { idx = i + 1; xk = cum; wk = wdt[i + 1]; }
                }
                float cumh = -5.f, yk = -5.f, hk = hgt[0];
                #pragma unroll
                for (int i = 0; i < 7; i++) {
                    cumh += hgt[i];
                    if (idx > i) { yk = cumh; hk = hgt[i + 1]; }
                }
                float sA = acc[16], sB = acc[17];
                #pragma unroll
                for (int i = 1; i < 8; i++)
                    if (idx >= i) { sA = acc[16 + i]; sB = acc[17 + i]; }
                const float dk  = 1e-4f + softplus_f(sA);
                const float dk1 = 1e-4f + softplus_f(sB);

                const float rwk  = 1.f / wk;
                const float xi   = (xc - xk) * rwk;
                const float om   = 1.f - xi;
                const float sk   = hk * rwk;
                const float xiom = xi * om;
                const float den  = sk + (dk1 + dk - 2.f * sk) * xiom;
                const float rden = 1.f / den;
                const float num  = sk * xi * xi + dk * xiom;
                const float y_in = yk + hk * num * rden;
                const float num2 = dk1 * xi * xi + 2.f * sk * xiom + dk * om * om;
                const float ld_in = __logf(sk * sk * num2 * rden * rden);

                if (vr) out[(row0 + row) * 64 + 32 + c * 4 + q] = inside ? y_in : xt;

                float ldv = inside ? ld_in : 0.f;
                ldv += __shfl_xor_sync(0xffffffffu, ldv, 1);
                ldv += __shfl_xor_sync(0xffffffffu, ldv, 2);
                if (q == 0) LDS[row] += ldv;
            }
            __syncthreads();
        }

        if (c < 7) {
            stage_u<64>(WA, nw, 64);        cp_commit();     // next k0n0
            stage_u<64>(WB, nw + 4096, 40); cp_commit();     // next k0n1
        }
    }

    // ---- logdet + masked-column copy ----
    __syncthreads();
    if (tid < 128 && row0 + tid < B) out[(size_t)B * 64 + row0 + tid] = LDS[tid];
    for (int i = tid; i < 1024; i += THREADS) {
        int row = i >> 3, j = i & 7;
        if (row0 + row < B)
            *(float4*)(out + (row0 + row) * 64 + j * 4) =
                *(const float4*)(x + (row0 + row) * 64 + j * 4);
    }
}

// ---------------------------------------------------------------------------
extern "C" void kernel_launch(void* const* d_in, const int* in_sizes, int n_in,
                              void* d_out, int out_size)
{
    const float* x  = (const float*)d_in[0];
    const float* W1 = (const float*)d_in[1];
    const float* b1 = (const float*)d_in[2];
    const float* W2 = (const float*)d_in[3];
    const float* b2 = (const float*)d_in[4];
    const float* W3 = (const float*)d_in[5];
    const float* b3 = (const float*)d_in[6];
    const float* W4 = (const float*)d_in[7];
    const float* b4 = (const float*)d_in[8];
    float* out = (float*)d_out;

    const int B = in_sizes[0] / 64;

    prep_weights<<<(WPK_TOT + 255) / 256, 256>>>(W1, W2, W3, W4);

    cudaFuncSetAttribute(rqs_mma_kernel,
                         cudaFuncAttributeMaxDynamicSharedMemorySize, SMEM_BYTES);
    const int grid = (B + 127) / 128;
    rqs_mma_kernel<<<grid, THREADS, SMEM_BYTES>>>(x, b1, b2, b3, b4, out, B);
}

// round 9
// speedup vs baseline: 1.6115x; 1.5870x over previous
#include <cuda_runtime.h>
#include <cuda_fp16.h>
#include <cstdint>

// ===========================================================================
// MaskedCouplingRQS — Round 9: fp16 m16n8k16 GEMMs (same 10-bit mantissa as
// tf32 => same accuracy class), halving tensor instructions AND LDS bytes.
// R6 orchestration: 128 rows/CTA, 16 rows/warp (A rows warp-private),
// alternating WA/WB 64-row weight units, fused RQS spline epilogue.
// ===========================================================================

#define THREADS 256
#define SA_H 160                      // A stride in halves (320B ≡ 64 mod 128)
#define SW_H 96                       // W stride in halves (192B ≡ 64 mod 128)
#define SPP  104                      // P stride (floats)

// ---- smem byte offsets ----
#define A_B    0                      // 128*160*2 = 40960
#define WA_B   40960                  // 64*96*2  = 12288
#define WB_B   53248
#define P_B    65536                  // 128*104*4 = 53248
#define B1_B   118784
#define B2_B   119296
#define B3_B   119808
#define B4_B   120320                 // 800*4 = 3200
#define SMEM_BYTES 123520

// ---- packed fp16 weights (mma-interleaved) ----
#define WPK_W1 0                      // 2 units [64 rows][32 halves]
#define WPK_W2 4096                   // 4 units [64][64]: k0n0,k0n1,k1n0,k1n1
#define WPK_W3 20480
#define WPK_W4 36864                  // 8 x (k0n0[64],k0n1[40],k1n0[64],k1n1[40])
#define W4_CH  13312
#define WPK_TOT 143360
__device__ __half g_wpk[WPK_TOT];

// --------------------------- helpers ---------------------------------------
__device__ __forceinline__ void cp16(void* dst, const void* src) {
    uint32_t s = (uint32_t)__cvta_generic_to_shared(dst);
    asm volatile("cp.async.cg.shared.global [%0], [%1], 16;" :: "r"(s), "l"(src));
}
__device__ __forceinline__ void cp_commit() { asm volatile("cp.async.commit_group;"); }
template<int N>
__device__ __forceinline__ void cp_wait() {
    asm volatile("cp.async.wait_group %0;" :: "n"(N) : "memory");
}
__device__ __forceinline__ void mma16(float* c, uint32_t a0, uint32_t a1,
                                      uint32_t a2, uint32_t a3,
                                      uint32_t b0, uint32_t b1) {
    asm volatile(
        "mma.sync.aligned.m16n8k16.row.col.f32.f16.f16.f32 "
        "{%0,%1,%2,%3}, {%4,%5,%6,%7}, {%8,%9}, {%0,%1,%2,%3};"
        : "+f"(c[0]), "+f"(c[1]), "+f"(c[2]), "+f"(c[3])
        : "r"(a0), "r"(a1), "r"(a2), "r"(a3), "r"(b0), "r"(b1));
}
__device__ __forceinline__ float softplus_f(float v) {
    return fmaxf(v, 0.f) + __logf(1.f + __expf(-fabsf(v)));
}
// packed half position for logical k within a 64-col row (bijection, verified):
//   rel=k&31: pos = 32*(k>>5) + ((rel>>1)&3)*8 + (rel>>3)*2 + (rel&1)
__device__ __forceinline__ int hpos(int k) {
    int rel = k & 31;
    return ((k >> 5) << 5) + (((rel >> 1) & 3) << 3) + ((rel >> 3) << 1) + (rel & 1);
}

// ---------------------------------------------------------------------------
// prep: pack all weights to fp16 in mma-native order.
// Inverse map at packed position p within a row: kg=p>>5, rem=p&31,
//   m=rem>>3, h=rem&7 -> k = kg*32 + 2m + (h&1) + 8*(h>>1)
// ---------------------------------------------------------------------------
__global__ void prep_weights(const float* __restrict__ W1, const float* __restrict__ W2,
                             const float* __restrict__ W3, const float* __restrict__ W4)
{
    int idx = blockIdx.x * blockDim.x + threadIdx.x;
    if (idx >= WPK_TOT) return;
    float v;
    if (idx < WPK_W2) {                               // W1: 128 rows x 32 halves
        int n = idx >> 5, p = idx & 31;
        int m = p >> 3, h = p & 7;
        int k = 2 * m + (h & 1) + 8 * (h >> 1);
        v = W1[n * 32 + k];
    } else if (idx < WPK_W4) {                        // W2/W3: 4 units [64][64]
        int t = idx - WPK_W2;
        const float* W = (t < 16384) ? W2 : W3;
        int r = t & 16383;
        int u = r >> 12, rr = r & 4095;
        int nloc = rr >> 6, p = rr & 63;
        int kg = p >> 5, rem = p & 31, m = rem >> 3, h = rem & 7;
        int kl = kg * 32 + 2 * m + (h & 1) + 8 * (h >> 1);
        int n = (u & 1) * 64 + nloc;
        int k = (u >> 1) * 64 + kl;
        v = W[n * 128 + k];
    } else {                                          // W4: 8 chunks, N padded 104
        int t = idx - WPK_W4;
        int c = t / W4_CH, r = t % W4_CH;
        int kh, nu, rr;
        if      (r < 4096)  { kh = 0; nu = 0; rr = r; }
        else if (r < 6656)  { kh = 0; nu = 1; rr = r - 4096; }
        else if (r < 10752) { kh = 1; nu = 0; rr = r - 6656; }
        else                { kh = 1; nu = 1; rr = r - 10752; }
        int nloc = rr >> 6, p = rr & 63;
        int kg = p >> 5, rem = p & 31, m = rem >> 3, h = rem & 7;
        int kl = kg * 32 + 2 * m + (h & 1) + 8 * (h >> 1);
        int n = nu * 64 + nloc;
        int k = kh * 64 + kl;
        v = (n < 100) ? W4[(size_t)(c * 100 + n) * 128 + k] : 0.f;
    }
    g_wpk[idx] = __float2half_rn(v);
}

// ---------------------------------------------------------------------------
// stage a packed unit: nrows rows of ROWH halves into W buffer (stride SW_H)
template<int ROWH>
__device__ __forceinline__ void stage_u(__half* dst, const __half* src, int nrows) {
    constexpr int CH = ROWH / 8;                       // 16B chunks per row
    for (int i = threadIdx.x; i < nrows * CH; i += THREADS) {
        int row = i / CH, j = i - row * CH;
        cp16(dst + row * SW_H + j * 8, src + row * ROWH + j * 8);
    }
}

// MMA over one staged unit: As pre-offset to (R0+g) row + m*8 halves.
template<int NT, int KG>
__device__ __forceinline__ void mma_unit(const __half* As, const __half* Wg, float* C) {
    #pragma unroll
    for (int kg = 0; kg < KG; kg++) {
        uint4 X = *(const uint4*)(As + kg * 32);              // row g
        uint4 Y = *(const uint4*)(As + 8 * SA_H + kg * 32);   // row g+8
        #pragma unroll
        for (int nt = 0; nt < NT; nt++) {
            uint4 Wv = *(const uint4*)(Wg + nt * 8 * SW_H + kg * 32);
            mma16(C + nt * 4, X.x, Y.x, X.y, Y.y, Wv.x, Wv.y);   // k16 group 0
            mma16(C + nt * 4, X.z, Y.z, X.w, Y.w, Wv.z, Wv.w);   // k16 group 1
        }
    }
}

// relu(C + bias) -> packed fp16 A tile (own 16 rows).
// col pair (8nt+2m, +1) lands at half-offset (nt>>2)*32 + m*8 + (nt&3)*2.
__device__ __forceinline__ void relu_store(const float* C, const float* bs,
                                           __half* Ah, int R0) {
    const int lane = threadIdx.x & 31;
    const int g = lane >> 2, m = lane & 3;
    #pragma unroll
    for (int nt = 0; nt < 16; nt++) {
        const int c0 = nt * 8 + 2 * m;
        const float b0 = bs[c0], b1 = bs[c0 + 1];
        const int off = ((nt >> 2) << 5) + (m << 3) + ((nt & 3) << 1);
        __half2 lo = __floats2half2_rn(fmaxf(C[nt*4+0] + b0, 0.f),
                                       fmaxf(C[nt*4+1] + b1, 0.f));
        __half2 hi = __floats2half2_rn(fmaxf(C[nt*4+2] + b0, 0.f),
                                       fmaxf(C[nt*4+3] + b1, 0.f));
        *(__half2*)(Ah + (R0 + g) * SA_H + off)     = lo;
        *(__half2*)(Ah + (R0 + g + 8) * SA_H + off) = hi;
    }
}

__device__ __forceinline__ void p_store(const float* C, float* P, int R0) {
    const int lane = threadIdx.x & 31;
    const int g = lane >> 2, m = lane & 3;
    #pragma unroll
    for (int nt = 0; nt < 13; nt++) {
        const int c0 = nt * 8 + 2 * m, c1 = c0 + 1;
        P[(R0 + g) * SPP + c0]     = C[nt*4+0];
        P[(R0 + g) * SPP + c1]     = C[nt*4+1];
        P[(R0 + g + 8) * SPP + c0] = C[nt*4+2];
        P[(R0 + g + 8) * SPP + c1] = C[nt*4+3];
    }
}

// ---------------------------------------------------------------------------
__global__ __launch_bounds__(THREADS, 1)
void rqs_mma_kernel(const float* __restrict__ x,
                    const float* __restrict__ b1, const float* __restrict__ b2,
                    const float* __restrict__ b3, const float* __restrict__ b4,
                    float* __restrict__ out, int B)
{
    extern __shared__ char smem[];
    __half* Ah  = (__half*)(smem + A_B);
    __half* WA  = (__half*)(smem + WA_B);
    __half* WB  = (__half*)(smem + WB_B);
    float*  Psm = (float*)(smem + P_B);
    float*  B1S = (float*)(smem + B1_B);
    float*  B2S = (float*)(smem + B2_B);
    float*  B3S = (float*)(smem + B3_B);
    float*  B4S = (float*)(smem + B4_B);

    const int tid  = threadIdx.x;
    const int lane = tid & 31;
    const int g    = lane >> 2, m = lane & 3;
    const int R0   = (tid >> 5) * 16;
    const long row0 = (long)blockIdx.x * 128;

    const __half* aw = Ah + (R0 + g) * SA_H + m * 8;   // own-warp A base
    const int woff = g * SW_H + m * 8;

    // ---- prologue staging ----
    stage_u<32>(WA, g_wpk + WPK_W1, 64);               // W1 n0
    for (int i = tid; i < 32; i += THREADS) {
        cp16(B1S + i * 4, b1 + i * 4);
        cp16(B2S + i * 4, b2 + i * 4);
        cp16(B3S + i * 4, b3 + i * 4);
    }
    for (int i = tid; i < 200; i += THREADS) cp16(B4S + i * 4, b4 + i * 4);
    cp_commit();
    stage_u<32>(WB, g_wpk + WPK_W1 + 2048, 64); cp_commit();   // W1 n1

    // ---- x_masked -> packed fp16 A ----
    for (int i = tid; i < 1024; i += THREADS) {
        int row = i >> 3, j = i & 7;
        float4 v = make_float4(0.f, 0.f, 0.f, 0.f);
        if (row0 + row < B) v = *(const float4*)(x + (row0 + row) * 64 + j * 4);
        __half* Ar = Ah + row * SA_H;
        Ar[hpos(j * 4 + 0)] = __float2half_rn(v.x);
        Ar[hpos(j * 4 + 1)] = __float2half_rn(v.y);
        Ar[hpos(j * 4 + 2)] = __float2half_rn(v.z);
        Ar[hpos(j * 4 + 3)] = __float2half_rn(v.w);
    }

    cp_wait<0>(); __syncthreads();

    float C[64];

    // ================= Layer 1 (K=32) =================
    #pragma unroll
    for (int i = 0; i < 64; i++) C[i] = 0.f;
    mma_unit<8, 1>(aw, WA + woff, C);
    __syncthreads(); stage_u<64>(WA, g_wpk + WPK_W2, 64); cp_commit();         // W2 k0n0
    mma_unit<8, 1>(aw, WB + woff, C + 32);
    relu_store(C, B1S, Ah, R0);                                                // h1
    __syncthreads(); stage_u<64>(WB, g_wpk + WPK_W2 + 4096, 64); cp_commit();  // W2 k0n1

    // ================= Layer 2 =================
    #pragma unroll
    for (int i = 0; i < 64; i++) C[i] = 0.f;
    cp_wait<1>(); __syncthreads();
    mma_unit<8, 2>(aw, WA + woff, C);
    __syncthreads(); stage_u<64>(WA, g_wpk + WPK_W2 + 8192, 64); cp_commit();  // k1n0
    cp_wait<1>(); __syncthreads();
    mma_unit<8, 2>(aw, WB + woff, C + 32);
    __syncthreads(); stage_u<64>(WB, g_wpk + WPK_W2 + 12288, 64); cp_commit(); // k1n1
    cp_wait<1>(); __syncthreads();
    mma_unit<8, 2>(aw + 64, WA + woff, C);
    __syncthreads(); stage_u<64>(WA, g_wpk + WPK_W3, 64); cp_commit();         // W3 k0n0
    cp_wait<1>(); __syncthreads();
    mma_unit<8, 2>(aw + 64, WB + woff, C + 32);
    relu_store(C, B2S, Ah, R0);                                                // h2
    __syncthreads(); stage_u<64>(WB, g_wpk + WPK_W3 + 4096, 64); cp_commit();  // W3 k0n1

    // ================= Layer 3 =================
    #pragma unroll
    for (int i = 0; i < 64; i++) C[i] = 0.f;
    cp_wait<1>(); __syncthreads();
    mma_unit<8, 2>(aw, WA + woff, C);
    __syncthreads(); stage_u<64>(WA, g_wpk + WPK_W3 + 8192, 64); cp_commit();  // k1n0
    cp_wait<1>(); __syncthreads();
    mma_unit<8, 2>(aw, WB + woff, C + 32);
    __syncthreads(); stage_u<64>(WB, g_wpk + WPK_W3 + 12288, 64); cp_commit(); // k1n1
    cp_wait<1>(); __syncthreads();
    mma_unit<8, 2>(aw + 64, WA + woff, C);
    __syncthreads(); stage_u<64>(WA, g_wpk + WPK_W4, 64); cp_commit();         // W4c0 k0n0
    cp_wait<1>(); __syncthreads();
    mma_unit<8, 2>(aw + 64, WB + woff, C + 32);
    relu_store(C, B3S, Ah, R0);                                                // h3
    __syncthreads(); stage_u<64>(WB, g_wpk + WPK_W4 + 4096, 40); cp_commit();  // W4c0 k0n1

    // ================= Layer 4 + spline, 8 chunks =================
    const float MINB = 1e-4f;
    const float FREE = 10.f - 8.f * 1e-4f;
    const int trow = tid >> 1;
    float ldsum = 0.f;

    #pragma unroll 1
    for (int c = 0; c < 8; c++) {
        const __half* cw = g_wpk + WPK_W4 + c * W4_CH;
        const __half* nw = g_wpk + WPK_W4 + (c + 1) * W4_CH;

        #pragma unroll
        for (int i = 0; i < 52; i++) C[i] = 0.f;

        cp_wait<0>(); __syncthreads();                       // k0n0 + k0n1 landed
        mma_unit<8, 2>(aw, WA + woff, C);
        __syncthreads(); stage_u<64>(WA, cw + 6656, 64);  cp_commit();   // k1n0
        mma_unit<5, 2>(aw, WB + woff, C + 32);
        __syncthreads(); stage_u<64>(WB, cw + 10752, 40); cp_commit();   // k1n1
        cp_wait<1>(); __syncthreads();
        mma_unit<8, 2>(aw + 64, WA + woff, C);
        cp_wait<0>(); __syncthreads();
        mma_unit<5, 2>(aw + 64, WB + woff, C + 32);
        __syncthreads();                                     // W bufs free
        if (c < 7) {                                         // overlap next-chunk k0
            stage_u<64>(WA, nw, 64);        cp_commit();
            stage_u<64>(WB, nw + 4096, 40); cp_commit();
        }
        p_store(C, Psm, R0);
        __syncthreads();

        // -------- spline epilogue: 2 (row,dim) tasks/thread --------
        #pragma unroll
        for (int j = 0; j < 2; j++) {
            const int q = 2 * (tid & 1) + j;
            const int t = c * 4 + q;

            float acc[25];
            #pragma unroll
            for (int p = 0; p < 25; p++)
                acc[p] = Psm[trow * SPP + q * 25 + p] + B4S[c * 100 + q * 25 + p];

            float mx = acc[0];
            #pragma unroll
            for (int i = 1; i < 8; i++) mx = fmaxf(mx, acc[i]);
            float wdt[8]; float Sw = 0.f;
            #pragma unroll
            for (int i = 0; i < 8; i++) { wdt[i] = __expf(acc[i] - mx); Sw += wdt[i]; }
            float mh = acc[8];
            #pragma unroll
            for (int i = 9; i < 16; i++) mh = fmaxf(mh, acc[i]);
            float hgt[8]; float Sh = 0.f;
            #pragma unroll
            for (int i = 0; i < 8; i++) { hgt[i] = __expf(acc[8 + i] - mh); Sh += hgt[i]; }
            const float fw = FREE / Sw, fh = FREE / Sh;
            #pragma unroll
            for (int i = 0; i < 8; i++) {
                wdt[i] = MINB + wdt[i] * fw;
                hgt[i] = MINB + hgt[i] * fh;
            }

            float xt = 0.f;
            const bool vr = (row0 + trow) < B;
            if (vr) xt = x[(row0 + trow) * 64 + 32 + t];
            const float xc = fminf(fmaxf(xt, -5.f), 5.f);
            const bool inside = (xt >= -5.f) && (xt <= 5.f);

            int idx = 0; float cum = -5.f, xk = -5.f, wk = wdt[0];
            #pragma unroll
            for (int i = 0; i < 7; i++) {
                cum += wdt[i];
                if (xc >= cum) { idx = i + 1; xk = cum; wk = wdt[i + 1]; }
            }
            float cumh = -5.f, yk = -5.f, hk = hgt[0];
            #pragma unroll
            for (int i = 0; i < 7; i++) {
                cumh += hgt[i];
                if (idx > i) { yk = cumh; hk = hgt[i + 1]; }
            }
            float sA = acc[16], sB = acc[17];
            #pragma unroll
            for (int i = 1; i < 8; i++)
                if (idx >= i) { sA = acc[16 + i]; sB = acc[17 + i]; }
            const float dk  = 1e-4f + softplus_f(sA);
            const float dk1 = 1e-4f + softplus_f(sB);

            const float rwk  = 1.f / wk;
            const float xi   = (xc - xk) * rwk;
            const float om   = 1.f - xi;
            const float sk   = hk * rwk;
            const float xiom = xi * om;
            const float den  = sk + (dk1 + dk - 2.f * sk) * xiom;
            const float rden = 1.f / den;
            const float num  = sk * xi * xi + dk * xiom;
            const float y_in = yk + hk * num * rden;
            const float num2 = dk1 * xi * xi + 2.f * sk * xiom + dk * om * om;
            const float ld_in = __logf(sk * sk * num2 * rden * rden);

            if (vr) out[(row0 + trow) * 64 + 32 + t] = inside ? y_in : xt;
            ldsum += inside ? ld_in : 0.f;
        }
        __syncthreads();                  // P reads done before next p_store
    }

    // ---- logdet: pair-reduce (tid, tid^1 share a row) ----
    ldsum += __shfl_xor_sync(0xFFFFFFFFu, ldsum, 1);
    if ((tid & 1) == 0 && row0 + trow < B)
        out[(size_t)B * 64 + row0 + trow] = ldsum;

    // ---- masked-column copy ----
    for (int i = tid; i < 1024; i += THREADS) {
        int row = i >> 3, j = i & 7;
        if (row0 + row < B)
            *(float4*)(out + (row0 + row) * 64 + j * 4) =
                *(const float4*)(x + (row0 + row) * 64 + j * 4);
    }
}

// ---------------------------------------------------------------------------
extern "C" void kernel_launch(void* const* d_in, const int* in_sizes, int n_in,
                              void* d_out, int out_size)
{
    const float* x  = (const float*)d_in[0];
    const float* W1 = (const float*)d_in[1];
    const float* b1 = (const float*)d_in[2];
    const float* W2 = (const float*)d_in[3];
    const float* b2 = (const float*)d_in[4];
    const float* W3 = (const float*)d_in[5];
    const float* b3 = (const float*)d_in[6];
    const float* W4 = (const float*)d_in[7];
    const float* b4 = (const float*)d_in[8];
    float* out = (float*)d_out;

    const int B = in_sizes[0] / 64;

    prep_weights<<<(WPK_TOT + 255) / 256, 256>>>(W1, W2, W3, W4);

    cudaFuncSetAttribute(rqs_mma_kernel,
                         cudaFuncAttributeMaxDynamicSharedMemorySize, SMEM_BYTES);
    const int grid = (B + 127) / 128;
    rqs_mma_kernel<<<grid, THREADS, SMEM_BYTES>>>(x, b1, b2, b3, b4, out, B);
}